// round 15
// baseline (speedup 1.0000x reference)
#include <cuda_runtime.h>
#include <cuda_fp16.h>
#include <math.h>
#include <stdint.h>

#define B_   32
#define S_   64
#define T_   48
#define TD   47
#define V_   32000
#define E_   512
#define H_   1024
#define H3_  3072
#define NBLK 64

// ---------------- device scratch ----------------
__device__ float g_gi0  [B_*S_*H3_];
__device__ float g_giemb[TD*B_*H3_];
__device__ float g_h0   [2][B_*H_];
__device__ float g_h1   [2][B_*H_];
__device__ unsigned g_count;
// fp16 operands
__device__ __half g_embh [B_*S_*E_];
__device__ __half g_dembh[TD*B_*E_];
__device__ __half g_wih0eh[H3_*E_];
__device__ __half g_wih0dh[H3_*E_];
__device__ __half g_attnh [H_*H_];
__device__ __half g_ench [B_*S_*H_];
__device__ __half g_projh[B_*S_*H_];
__device__ __half g_wh[7][H3_*H_];
__device__ __half g_h0h[2][B_*H_];
__device__ __half g_h1h[2][B_*H_];
__device__ __half g_xh [B_*H_];
__device__ __half g_cath[TD*B_*2*H_];
__device__ __half g_owh[(size_t)V_*2*H_];

__global__ void k_reset() { g_count = 0u; }

// ---------------- helpers ----------------
__device__ __forceinline__ void mma16(float c[4], const uint32_t a[4], const uint32_t b[2]) {
    asm volatile(
        "mma.sync.aligned.m16n8k16.row.col.f32.f16.f16.f32 "
        "{%0,%1,%2,%3}, {%4,%5,%6,%7}, {%8,%9}, {%0,%1,%2,%3};\n"
        : "+f"(c[0]), "+f"(c[1]), "+f"(c[2]), "+f"(c[3])
        : "r"(a[0]), "r"(a[1]), "r"(a[2]), "r"(a[3]), "r"(b[0]), "r"(b[1]));
}

// ---------------- prep ----------------
__global__ void k_init(const int* __restrict__ src_ids, const float* __restrict__ enc_emb)
{
    int idx = blockIdx.x * blockDim.x + threadIdx.x;
    if (idx < B_*S_*E_) {
        int m = idx >> 9, k = idx & 511;
        g_embh[idx] = __float2half_rn(enc_emb[(size_t)src_ids[m] * E_ + k]);
    }
}
__global__ void k_demb(const int* __restrict__ tgt_ids, const float* __restrict__ dec_emb)
{
    int idx = blockIdx.x * blockDim.x + threadIdx.x;
    if (idx >= TD*B_*E_) return;
    int m = idx >> 9, k = idx & 511;
    int b = m & 31, t = m >> 5;
    g_dembh[idx] = __float2half_rn(dec_emb[(size_t)tgt_ids[b*T_ + t] * E_ + k]);
}
__global__ void k_wconv(const float* __restrict__ e_whh0, const float* __restrict__ e_wih1,
                        const float* __restrict__ e_whh1, const float* __restrict__ d_whh0,
                        const float* __restrict__ d_wih0, const float* __restrict__ d_wih1,
                        const float* __restrict__ d_whh1)
{
    int y = blockIdx.y;
    int idx = blockIdx.x * 256 + threadIdx.x;
    float v;
    if (y == 4) {
        int r = idx >> 10, c = idx & 1023;
        v = d_wih0[(size_t)r * (E_+H_) + E_ + c];
    } else {
        const float* src = (y==0) ? e_whh0 : (y==1) ? e_wih1 : (y==2) ? e_whh1
                         : (y==3) ? d_whh0 : (y==5) ? d_wih1 : d_whh1;
        v = src[idx];
    }
    g_wh[y][idx] = __float2half_rn(v);
}
__global__ void k_wconv2(const float* __restrict__ e_wih0, const float* __restrict__ d_wih0,
                         const float* __restrict__ attn_w)
{
    int y = blockIdx.y;
    int idx = blockIdx.x * 256 + threadIdx.x;
    if (y == 0) {
        g_wih0eh[idx] = __float2half_rn(e_wih0[idx]);
    } else if (y == 1) {
        int r = idx >> 9, c = idx & 511;
        g_wih0dh[idx] = __float2half_rn(d_wih0[(size_t)r * (E_+H_) + c]);
    } else {
        if (idx < H_*H_) g_attnh[idx] = __float2half_rn(attn_w[idx]);
    }
}
__global__ void k_owconv(const float* __restrict__ out_w)
{
    size_t i = ((size_t)blockIdx.x * 256 + threadIdx.x) * 8;
    float4 a = *(const float4*)(out_w + i);
    float4 b = *(const float4*)(out_w + i + 4);
    __half2 h0 = __floats2half2_rn(a.x, a.y);
    __half2 h1 = __floats2half2_rn(a.z, a.w);
    __half2 h2 = __floats2half2_rn(b.x, b.y);
    __half2 h3 = __floats2half2_rn(b.z, b.w);
    uint4 o;
    o.x = *(uint32_t*)&h0; o.y = *(uint32_t*)&h1;
    o.z = *(uint32_t*)&h2; o.w = *(uint32_t*)&h3;
    *(uint4*)(g_owh + i) = o;
}

// ---------------- grid barrier ----------------
__device__ __forceinline__ void gbar(unsigned &target) {
    __threadfence();
    __syncthreads();
    if (threadIdx.x == 0) {
        atomicAdd(&g_count, 1u);
        target += NBLK;
        while (*(volatile unsigned*)&g_count < target) { }
    }
    __syncthreads();
}

// ---------------- fp16 GEMV pass: 16 gate-rows per block (6 n-tiles) ----------------
__device__ __forceinline__ void gemv16(float acc[2][6][4],
        const __half* __restrict__ A, const __half* __restrict__ W,
        int jt0, int lane, int warp)
{
    int g = lane >> 2, tg = lane & 3;
    int kbeg = warp * 128;
    const __half* wr[6];
#pragma unroll
    for (int nt = 0; nt < 6; nt++)
        wr[nt] = W + (size_t)((nt >> 1) * H_ + jt0 + (nt & 1) * 8 + g) * H_;
#pragma unroll
    for (int kk = kbeg; kk < kbeg + 128; kk += 16) {
        uint32_t af[2][4];
#pragma unroll
        for (int mt = 0; mt < 2; mt++) {
            const __half* ap = A + (size_t)(mt*16 + g) * H_ + kk + 2*tg;
            af[mt][0] = __ldcg((const unsigned*)ap);
            af[mt][1] = __ldcg((const unsigned*)(ap + 8*H_));
            af[mt][2] = __ldcg((const unsigned*)(ap + 8));
            af[mt][3] = __ldcg((const unsigned*)(ap + 8*H_ + 8));
        }
#pragma unroll
        for (int nt = 0; nt < 6; nt++) {
            uint32_t bf[2];
            bf[0] = __ldg((const unsigned*)(wr[nt] + kk + 2*tg));
            bf[1] = __ldg((const unsigned*)(wr[nt] + kk + 2*tg + 8));
            mma16(acc[0][nt], af[0], bf);
            mma16(acc[1][nt], af[1], bf);
        }
    }
}

// reduce 8 warps' C[32 batch x 48 gaterow] frags -> s_out[gate*512 + b*16 + j]
// two-round accumulation (R6-proven layout, padded stride 17)
__device__ __forceinline__ void reduce6(const float acc[2][6][4],
        float* s_red, float* s_out)
{
    int lane = threadIdx.x & 31, warp = threadIdx.x >> 5;
    int g = lane >> 2, tg = lane & 3;
    float* base = s_red + (warp & 3) * 1632;
    if (warp < 4) {
#pragma unroll
        for (int mt = 0; mt < 2; mt++)
#pragma unroll
        for (int nt = 0; nt < 6; nt++)
#pragma unroll
        for (int q = 0; q < 4; q++) {
            int row = mt*16 + g + ((q >> 1) << 3);
            int col = nt*8 + 2*tg + (q & 1);
            int e = (col >> 4) * 512 + row * 16 + (col & 15);
            base[(e >> 4) * 17 + (e & 15)] = acc[mt][nt][q];
        }
    }
    __syncthreads();
    if (warp >= 4) {
#pragma unroll
        for (int mt = 0; mt < 2; mt++)
#pragma unroll
        for (int nt = 0; nt < 6; nt++)
#pragma unroll
        for (int q = 0; q < 4; q++) {
            int row = mt*16 + g + ((q >> 1) << 3);
            int col = nt*8 + 2*tg + (q & 1);
            int e = (col >> 4) * 512 + row * 16 + (col & 15);
            base[(e >> 4) * 17 + (e & 15)] += acc[mt][nt][q];
        }
    }
    __syncthreads();
    int tid = threadIdx.x;
#pragma unroll
    for (int i = 0; i < 6; i++) {
        int e = tid + i * 256;
        int ph = (e >> 4) * 17 + (e & 15);
        s_out[e] = s_red[ph] + s_red[1632 + ph] + s_red[3264 + ph] + s_red[4896 + ph];
    }
    __syncthreads();
}

__device__ __forceinline__ float sigf(float x) { return 1.f / (1.f + expf(-x)); }

// ---------------- persistent encoder: pipelined h0(t) + h1(t-1) per phase ----------------
__global__ void __launch_bounds__(256) k_enc(
    const float* __restrict__ bhh0, const float* __restrict__ bih1,
    const float* __restrict__ bhh1)
{
    __shared__ float s_red[4*1632];
    __shared__ float s_g0[1536];
    __shared__ float s_gi[1536];
    __shared__ float s_gh[1536];
    int tid = threadIdx.x, lane = tid & 31, warp = tid >> 5;
    int jt0 = blockIdx.x * 16;
    unsigned target = 0;

    {   // zero init: 64 blocks * 512 = B_*H_
        int i0 = blockIdx.x * 512 + tid;
        int i1 = i0 + 256;
        g_h0[0][i0] = 0.f; g_h1[0][i0] = 0.f;
        g_h0[0][i1] = 0.f; g_h1[0][i1] = 0.f;
        g_h0h[0][i0] = __float2half_rn(0.f); g_h1h[0][i0] = __float2half_rn(0.f);
        g_h0h[0][i1] = __float2half_rn(0.f); g_h1h[0][i1] = __float2half_rn(0.f);
    }
    gbar(target);

    for (int t = 0; t <= S_; t++) {
        int p = t & 1;
        if (t < S_) {
            float a[2][6][4] = {};
            gemv16(a, g_h0h[p], g_wh[0], jt0, lane, warp);
            reduce6(a, s_red, s_g0);
        }
        if (t > 0) {
            float a[2][6][4] = {};
            gemv16(a, g_h0h[p], g_wh[1], jt0, lane, warp);
            reduce6(a, s_red, s_gi);
            float a2[2][6][4] = {};
            gemv16(a2, g_h1h[1-p], g_wh[2], jt0, lane, warp);
            reduce6(a2, s_red, s_gh);
        }
        if (t < S_) {
            for (int v = tid; v < 512; v += 256) {
                int j = v & 15, b = v >> 4;
                int jg = jt0 + j;
                const float* gi = g_gi0 + ((size_t)b * S_ + t) * H3_;
                float r = sigf(gi[jg]      + s_g0[        b*16 + j] + bhh0[jg]);
                float z = sigf(gi[H_ + jg] + s_g0[ 512 +  b*16 + j] + bhh0[H_ + jg]);
                float ghn =                  s_g0[1024 +  b*16 + j] + bhh0[2*H_ + jg];
                float n = tanhf(gi[2*H_ + jg] + r * ghn);
                float hp = __ldcg(&g_h0[p][b*H_ + jg]);
                float h = (1.f - z) * n + z * hp;
                g_h0[1-p][b*H_ + jg] = h;
                g_h0h[1-p][b*H_ + jg] = __float2half_rn(h);
            }
        }
        if (t > 0) {
            for (int v = tid; v < 512; v += 256) {
                int j = v & 15, b = v >> 4;
                int jg = jt0 + j;
                float r = sigf(s_gi[        b*16 + j] + bih1[jg]
                             + s_gh[        b*16 + j] + bhh1[jg]);
                float z = sigf(s_gi[ 512 +  b*16 + j] + bih1[H_ + jg]
                             + s_gh[ 512 +  b*16 + j] + bhh1[H_ + jg]);
                float gin = s_gi[1024 + b*16 + j] + bih1[2*H_ + jg];
                float ghn = s_gh[1024 + b*16 + j] + bhh1[2*H_ + jg];
                float n = tanhf(gin + r * ghn);
                float hp = __ldcg(&g_h1[1-p][b*H_ + jg]);
                float h = (1.f - z) * n + z * hp;
                g_h1[p][b*H_ + jg] = h;
                g_h1h[p][b*H_ + jg] = __float2half_rn(h);
                g_ench[((size_t)b * S_ + (t-1)) * H_ + jg] = __float2half_rn(h);
            }
        }
        gbar(target);
    }
}

// ---------------- persistent decoder: 3 phases/step ----------------
__global__ void __launch_bounds__(256) k_dec(
    const int* __restrict__ src_ids,
    const float* __restrict__ bhh0, const float* __restrict__ bih1,
    const float* __restrict__ bhh1)
{
    __shared__ float s_red[4*1632];
    __shared__ float s_gi[1536];
    __shared__ float s_gh[1536];
    __shared__ float s_ev[S_];
    __shared__ float s_mxv[2];
    int tid = threadIdx.x, lane = tid & 31, warp = tid >> 5;
    int nb = blockIdx.x;
    int jt0 = nb * 16;
    int b = nb >> 1, hbase = (nb & 1) * 512;   // 2 blocks per batch
    unsigned target = 0;

    for (int t = 0; t < TD; t++) {
        int p = t & 1;
        {   // ---- P_ab: scores (fp16 proj, redundant x2) + softmax + ctx (fp16 enc)
            float* hc = s_red;
            for (int i = tid; i < H_; i += 256)
                hc[i] = __ldcg(&g_h1[p][b*H_ + i]);
            __syncthreads();
#pragma unroll
            for (int ss = 0; ss < 8; ss++) {
                int s = warp * 8 + ss;
                const __half2* ph2 = (const __half2*)(g_projh + (size_t)(b*S_ + s)*H_);
                float acc = 0.f;
#pragma unroll 8
                for (int k2 = lane; k2 < H_/2; k2 += 32) {
                    float2 pf = __half22float2(__ldg(ph2 + k2));
                    acc += pf.x * hc[2*k2] + pf.y * hc[2*k2 + 1];
                }
#pragma unroll
                for (int o = 16; o; o >>= 1) acc += __shfl_xor_sync(0xffffffffu, acc, o);
                if (lane == 0)
                    s_ev[s] = (src_ids[b*S_ + s] != 0) ? acc : -1e9f;
            }
            __syncthreads();
            if (tid == 0) {
                float mx = -1e30f;
#pragma unroll
                for (int s = 0; s < S_; s++) mx = fmaxf(mx, s_ev[s]);
                s_mxv[0] = mx;
            }
            __syncthreads();
            if (tid < S_) s_ev[tid] = expf(s_ev[tid] - s_mxv[0]);
            __syncthreads();
            if (tid == 0) {
                float su = 0.f;
#pragma unroll
                for (int s = 0; s < S_; s++) su += s_ev[s];
                s_mxv[1] = 1.f / su;
            }
            __syncthreads();
            float inv = s_mxv[1];
#pragma unroll
            for (int i = 0; i < 2; i++) {
                int h = hbase + tid + i * 256;
                const __half* eph = g_ench + (size_t)b * S_ * H_ + h;
                float a = 0.f;
#pragma unroll 8
                for (int s = 0; s < S_; s++)
                    a += s_ev[s] * __half2float(__ldg(eph + (size_t)s * H_));
                a *= inv;
                __half ah = __float2half_rn(a);
                g_xh[b*H_ + h] = ah;
                g_cath[((size_t)t * B_ + b) * (2*H_) + H_ + h] = ah;
            }
        }
        gbar(target);
        {   // ---- P_c: layer0
            float ai[2][6][4] = {};
            gemv16(ai, g_xh, g_wh[4], jt0, lane, warp);
            reduce6(ai, s_red, s_gi);
            float ahh[2][6][4] = {};
            gemv16(ahh, g_h0h[p], g_wh[3], jt0, lane, warp);
            reduce6(ahh, s_red, s_gh);
            for (int v = tid; v < 512; v += 256) {
                int j = v & 15, bb = v >> 4;
                int jg = jt0 + j;
                const float* ge = g_giemb + ((size_t)t * B_ + bb) * H3_;
                float r = sigf(s_gi[        bb*16 + j] + ge[jg]
                             + s_gh[        bb*16 + j] + bhh0[jg]);
                float z = sigf(s_gi[ 512 +  bb*16 + j] + ge[H_ + jg]
                             + s_gh[ 512 +  bb*16 + j] + bhh0[H_ + jg]);
                float ghn = s_gh[1024 + bb*16 + j] + bhh0[2*H_ + jg];
                float gin = s_gi[1024 + bb*16 + j] + ge[2*H_ + jg];
                float n = tanhf(gin + r * ghn);
                float hp = __ldcg(&g_h0[p][bb*H_ + jg]);
                float h = (1.f - z) * n + z * hp;
                g_h0[1-p][bb*H_ + jg] = h;
                g_h0h[1-p][bb*H_ + jg] = __float2half_rn(h);
            }
        }
        gbar(target);
        {   // ---- P_d: layer1
            float ai[2][6][4] = {};
            gemv16(ai, g_h0h[1-p], g_wh[5], jt0, lane, warp);
            reduce6(ai, s_red, s_gi);
            float ahh[2][6][4] = {};
            gemv16(ahh, g_h1h[p], g_wh[6], jt0, lane, warp);
            reduce6(ahh, s_red, s_gh);
            for (int v = tid; v < 512; v += 256) {
                int j = v & 15, bb = v >> 4;
                int jg = jt0 + j;
                float r = sigf(s_gi[        bb*16 + j] + bih1[jg]
                             + s_gh[        bb*16 + j] + bhh1[jg]);
                float z = sigf(s_gi[ 512 +  bb*16 + j] + bih1[H_ + jg]
                             + s_gh[ 512 +  bb*16 + j] + bhh1[H_ + jg]);
                float gin = s_gi[1024 + bb*16 + j] + bih1[2*H_ + jg];
                float ghn = s_gh[1024 + bb*16 + j] + bhh1[2*H_ + jg];
                float n = tanhf(gin + r * ghn);
                float hp = __ldcg(&g_h1[p][bb*H_ + jg]);
                float h = (1.f - z) * n + z * hp;
                g_h1[1-p][bb*H_ + jg] = h;
                g_h1h[1-p][bb*H_ + jg] = __float2half_rn(h);
                g_cath[((size_t)t * B_ + bb) * (2*H_) + jg] = __float2half_rn(h);
            }
        }
        gbar(target);
    }
}

// ---------------- fp16 GEMM (R14-proven), 3 store modes ----------------
template<int MODE>
__global__ __launch_bounds__(256, 2)
void k_gemm16(const __half* __restrict__ A, int lda,
              const __half* __restrict__ W, int ldw,
              const float* __restrict__ bias, float* __restrict__ Cf,
              __half* __restrict__ Ch, int M, int N, int K)
{
    __shared__ __half As[2][128*40];
    __shared__ __half Bs[2][128*40];
    const int tid = threadIdx.x;
    const int m0 = blockIdx.x * 128;
    const int n0 = blockIdx.y * 128;
    const int warp = tid >> 5, lane = tid & 31;
    const int g = lane >> 2, tg = lane & 3;
    const int wm = (warp >> 2) * 64, wn = (warp & 3) * 32;

    const int lrow = tid >> 1;
    const int lo   = (tid & 1) * 16;
    int ar = m0 + lrow; if (ar >= M) ar = M - 1;
    const __half* ag = A + (size_t)ar * lda + lo;
    const __half* bg = W + (size_t)(n0 + lrow) * ldw + lo;
    uint32_t sa = (uint32_t)__cvta_generic_to_shared(&As[0][lrow*40 + lo]);
    uint32_t sb = (uint32_t)__cvta_generic_to_shared(&Bs[0][lrow*40 + lo]);
    const uint32_t ssz = 128*40*2;

    float acc[4][4][4];
#pragma unroll
    for (int i = 0; i < 4; i++)
#pragma unroll
        for (int j = 0; j < 4; j++)
#pragma unroll
            for (int q = 0; q < 4; q++) acc[i][j][q] = 0.f;

    auto issue = [&](int st, int c) {
        uint32_t so = st ? ssz : 0;
        const __half* p0 = ag + c*32;
        const __half* p1 = bg + c*32;
        asm volatile("cp.async.cg.shared.global [%0], [%1], 16;\n" :: "r"(sa+so), "l"(p0));
        asm volatile("cp.async.cg.shared.global [%0], [%1], 16;\n" :: "r"(sa+so+16), "l"(p0+8));
        asm volatile("cp.async.cg.shared.global [%0], [%1], 16;\n" :: "r"(sb+so), "l"(p1));
        asm volatile("cp.async.cg.shared.global [%0], [%1], 16;\n" :: "r"(sb+so+16), "l"(p1+8));
    };

    const int nchunk = K / 32;
    issue(0, 0);
    asm volatile("cp.async.commit_group;\n");

    for (int c = 0; c < nchunk; c++) {
        if (c + 1 < nchunk) issue((c + 1) & 1, c + 1);
        asm volatile("cp.async.commit_group;\n");
        asm volatile("cp.async.wait_group 1;\n");
        __syncthreads();
        const __half* as = As[c & 1];
        const __half* bs = Bs[c & 1];
#pragma unroll
        for (int ks = 0; ks < 32; ks += 16) {
            uint32_t af[4][4], bf[4][2];
#pragma unroll
            for (int i = 0; i < 4; i++) {
                int r = wm + i*16 + g;
                af[i][0] = *(const uint32_t*)&as[r*40 + ks + 2*tg];
                af[i][1] = *(const uint32_t*)&as[(r+8)*40 + ks + 2*tg];
                af[i][2] = *(const uint32_t*)&as[r*40 + ks + 2*tg + 8];
                af[i][3] = *(const uint32_t*)&as[(r+8)*40 + ks + 2*tg + 8];
            }
#pragma unroll
            for (int j = 0; j < 4; j++) {
                int cc = wn + j*8 + g;
                bf[j][0] = *(const uint32_t*)&bs[cc*40 + ks + 2*tg];
                bf[j][1] = *(const uint32_t*)&bs[cc*40 + ks + 2*tg + 8];
            }
#pragma unroll
            for (int i = 0; i < 4; i++)
#pragma unroll
                for (int j = 0; j < 4; j++)
                    mma16(acc[i][j], af[i], bf[j]);
        }
        __syncthreads();
    }

#pragma unroll
    for (int i = 0; i < 4; i++) {
#pragma unroll
        for (int j = 0; j < 4; j++) {
            int n = n0 + wn + j*8 + 2*tg;
            float bv0 = (MODE == 2) ? 0.f : bias[n];
            float bv1 = (MODE == 2) ? 0.f : bias[n + 1];
#pragma unroll
            for (int half = 0; half < 2; half++) {
                int m = m0 + wm + i*16 + g + half*8;
                float v0 = acc[i][j][half*2]     + bv0;
                float v1 = acc[i][j][half*2 + 1] + bv1;
                if (m < M) {
                    if (MODE == 0) {
                        float* o = Cf + (size_t)m * N + n;
                        o[0] = v0; o[1] = v1;
                    } else if (MODE == 1) {
                        int bb = m & 31, tt = m >> 5;
                        float* o = Cf + (size_t)bb*TD*V_ + (size_t)tt*V_ + n;
                        o[0] = v0; o[1] = v1;
                    } else {
                        *(__half2*)(Ch + (size_t)m * N + n) = __floats2half2_rn(v0, v1);
                    }
                }
            }
        }
    }
}

// ---------------- host ----------------
extern "C" void kernel_launch(void* const* d_in, const int* in_sizes, int n_in,
                              void* d_out, int out_size)
{
    const int*   src_ids  = (const int*)d_in[0];
    const int*   tgt_ids  = (const int*)d_in[2];
    const float* enc_emb  = (const float*)d_in[3];
    const float* dec_emb  = (const float*)d_in[4];
    const float* enc_wih0 = (const float*)d_in[5];
    const float* enc_whh0 = (const float*)d_in[6];
    const float* enc_bih0 = (const float*)d_in[7];
    const float* enc_bhh0 = (const float*)d_in[8];
    const float* enc_wih1 = (const float*)d_in[9];
    const float* enc_whh1 = (const float*)d_in[10];
    const float* enc_bih1 = (const float*)d_in[11];
    const float* enc_bhh1 = (const float*)d_in[12];
    const float* dec_wih0 = (const float*)d_in[13];
    const float* dec_whh0 = (const float*)d_in[14];
    const float* dec_bih0 = (const float*)d_in[15];
    const float* dec_bhh0 = (const float*)d_in[16];
    const float* dec_wih1 = (const float*)d_in[17];
    const float* dec_whh1 = (const float*)d_in[18];
    const float* dec_bih1 = (const float*)d_in[19];
    const float* dec_bhh1 = (const float*)d_in[20];
    const float* attn_w   = (const float*)d_in[21];
    const float* out_w    = (const float*)d_in[22];
    const float* out_b    = (const float*)d_in[23];
    float* out = (float*)d_out;

    float *gi0, *giemb;
    __half *embh, *dembh, *wih0eh, *wih0dh, *attnh, *ench, *projh, *cath, *owh;
    cudaGetSymbolAddress((void**)&gi0,    g_gi0);
    cudaGetSymbolAddress((void**)&giemb,  g_giemb);
    cudaGetSymbolAddress((void**)&embh,   g_embh);
    cudaGetSymbolAddress((void**)&dembh,  g_dembh);
    cudaGetSymbolAddress((void**)&wih0eh, g_wih0eh);
    cudaGetSymbolAddress((void**)&wih0dh, g_wih0dh);
    cudaGetSymbolAddress((void**)&attnh,  g_attnh);
    cudaGetSymbolAddress((void**)&ench,   g_ench);
    cudaGetSymbolAddress((void**)&projh,  g_projh);
    cudaGetSymbolAddress((void**)&cath,   g_cath);
    cudaGetSymbolAddress((void**)&owh,    g_owh);

    // prep
    k_init<<<(B_*S_*E_ + 255)/256, 256>>>(src_ids, enc_emb);
    k_demb<<<(TD*B_*E_ + 255)/256, 256>>>(tgt_ids, dec_emb);
    k_wconv<<<dim3(H3_*H_/256, 7), 256>>>(enc_whh0, enc_wih1, enc_whh1,
                                          dec_whh0, dec_wih0, dec_wih1, dec_whh1);
    k_wconv2<<<dim3(H3_*E_/256, 3), 256>>>(enc_wih0, dec_wih0, attn_w);
    k_owconv<<<(V_*2*H_/8 + 255)/256, 256>>>(out_w);

    // batched input-gate GEMMs (fp16)
    k_gemm16<0><<<dim3((B_*S_)/128, H3_/128), 256>>>(
        embh, E_, wih0eh, E_, enc_bih0, gi0, nullptr, B_*S_, H3_, E_);
    k_gemm16<0><<<dim3((TD*B_ + 127)/128, H3_/128), 256>>>(
        dembh, E_, wih0dh, E_, dec_bih0, giemb, nullptr, TD*B_, H3_, E_);

    // persistent encoder (64 blocks, 16 rows each)
    k_reset<<<1, 1>>>();
    k_enc<<<NBLK, 256>>>(enc_bhh0, enc_bih1, enc_bhh1);

    // attention projection (fp16 in/out)
    k_gemm16<2><<<dim3((B_*S_)/128, H_/128), 256>>>(
        ench, H_, attnh, H_, nullptr, nullptr, projh, B_*S_, H_, H_);

    // persistent decoder (64 blocks)
    k_reset<<<1, 1>>>();
    k_dec<<<NBLK, 256>>>(src_ids, dec_bhh0, dec_bih1, dec_bhh1);

    // output projection (fp16, scatter to (B,TD,V))
    k_gemm16<1><<<dim3((TD*B_ + 127)/128, V_/128), 256>>>(
        cath, 2*H_, owh, 2*H_, out_b, out, nullptr, TD*B_, V_, 2*H_);
}

// round 16
// speedup vs baseline: 1.3632x; 1.3632x over previous
#include <cuda_runtime.h>
#include <cuda_fp16.h>
#include <math.h>
#include <stdint.h>

#define B_   32
#define S_   64
#define T_   48
#define TD   47
#define V_   32000
#define E_   512
#define H_   1024
#define H3_  3072
#define NBLK 128

// ---------------- device scratch ----------------
__device__ float g_gi0  [B_*S_*H3_];
__device__ float g_giemb[TD*B_*H3_];
__device__ float g_h0   [2][B_*H_];
__device__ float g_h1   [2][B_*H_];
__device__ unsigned g_count;
// fp16 operands
__device__ __half g_embh [B_*S_*E_];
__device__ __half g_dembh[TD*B_*E_];
__device__ __half g_wih0eh[H3_*E_];
__device__ __half g_wih0dh[H3_*E_];
__device__ __half g_attnh [H_*H_];
__device__ __half g_ench [B_*S_*H_];
__device__ __half g_projh[B_*S_*H_];
__device__ __half g_wh[7][H3_*H_];
__device__ __half g_h0h[2][B_*H_];
__device__ __half g_h1h[2][B_*H_];
__device__ __half g_xh [B_*H_];
__device__ __half g_cath[TD*B_*2*H_];
__device__ __half g_owh[(size_t)V_*2*H_];

__global__ void k_reset() { g_count = 0u; }

// ---------------- helpers ----------------
__device__ __forceinline__ void mma16(float c[4], const uint32_t a[4], const uint32_t b[2]) {
    asm volatile(
        "mma.sync.aligned.m16n8k16.row.col.f32.f16.f16.f32 "
        "{%0,%1,%2,%3}, {%4,%5,%6,%7}, {%8,%9}, {%0,%1,%2,%3};\n"
        : "+f"(c[0]), "+f"(c[1]), "+f"(c[2]), "+f"(c[3])
        : "r"(a[0]), "r"(a[1]), "r"(a[2]), "r"(a[3]), "r"(b[0]), "r"(b[1]));
}

// ---------------- prep ----------------
__global__ void k_init(const int* __restrict__ src_ids, const float* __restrict__ enc_emb)
{
    int idx = blockIdx.x * blockDim.x + threadIdx.x;
    if (idx < B_*S_*E_) {
        int m = idx >> 9, k = idx & 511;
        g_embh[idx] = __float2half_rn(enc_emb[(size_t)src_ids[m] * E_ + k]);
    }
}
__global__ void k_demb(const int* __restrict__ tgt_ids, const float* __restrict__ dec_emb)
{
    int idx = blockIdx.x * blockDim.x + threadIdx.x;
    if (idx >= TD*B_*E_) return;
    int m = idx >> 9, k = idx & 511;
    int b = m & 31, t = m >> 5;
    g_dembh[idx] = __float2half_rn(dec_emb[(size_t)tgt_ids[b*T_ + t] * E_ + k]);
}
__global__ void k_wconv(const float* __restrict__ e_whh0, const float* __restrict__ e_wih1,
                        const float* __restrict__ e_whh1, const float* __restrict__ d_whh0,
                        const float* __restrict__ d_wih0, const float* __restrict__ d_wih1,
                        const float* __restrict__ d_whh1)
{
    int y = blockIdx.y;
    int idx = blockIdx.x * 256 + threadIdx.x;
    float v;
    if (y == 4) {
        int r = idx >> 10, c = idx & 1023;
        v = d_wih0[(size_t)r * (E_+H_) + E_ + c];
    } else {
        const float* src = (y==0) ? e_whh0 : (y==1) ? e_wih1 : (y==2) ? e_whh1
                         : (y==3) ? d_whh0 : (y==5) ? d_wih1 : d_whh1;
        v = src[idx];
    }
    g_wh[y][idx] = __float2half_rn(v);
}
__global__ void k_wconv2(const float* __restrict__ e_wih0, const float* __restrict__ d_wih0,
                         const float* __restrict__ attn_w)
{
    int y = blockIdx.y;
    int idx = blockIdx.x * 256 + threadIdx.x;
    if (y == 0) {
        g_wih0eh[idx] = __float2half_rn(e_wih0[idx]);
    } else if (y == 1) {
        int r = idx >> 9, c = idx & 511;
        g_wih0dh[idx] = __float2half_rn(d_wih0[(size_t)r * (E_+H_) + c]);
    } else {
        if (idx < H_*H_) g_attnh[idx] = __float2half_rn(attn_w[idx]);
    }
}
__global__ void k_owconv(const float* __restrict__ out_w)
{
    size_t i = ((size_t)blockIdx.x * 256 + threadIdx.x) * 8;
    float4 a = *(const float4*)(out_w + i);
    float4 b = *(const float4*)(out_w + i + 4);
    __half2 h0 = __floats2half2_rn(a.x, a.y);
    __half2 h1 = __floats2half2_rn(a.z, a.w);
    __half2 h2 = __floats2half2_rn(b.x, b.y);
    __half2 h3 = __floats2half2_rn(b.z, b.w);
    uint4 o;
    o.x = *(uint32_t*)&h0; o.y = *(uint32_t*)&h1;
    o.z = *(uint32_t*)&h2; o.w = *(uint32_t*)&h3;
    *(uint4*)(g_owh + i) = o;
}

// ---------------- grid barrier (proven) ----------------
__device__ __forceinline__ void gbar(unsigned &target) {
    __threadfence();
    __syncthreads();
    if (threadIdx.x == 0) {
        atomicAdd(&g_count, 1u);
        target += NBLK;
        while (*(volatile unsigned*)&g_count < target) { }
    }
    __syncthreads();
}

// ---------------- fp16 GEMV pass (R12-proven) ----------------
__device__ __forceinline__ void gemv16(float acc[2][3][4],
        const __half* __restrict__ A, const __half* __restrict__ W,
        int jt0, int lane, int warp)
{
    int g = lane >> 2, tg = lane & 3;
    int kbeg = warp * 128;
    const __half* w0 = W + (size_t)(jt0 + g) * H_;
    const __half* w1 = W + (size_t)(H_ + jt0 + g) * H_;
    const __half* w2 = W + (size_t)(2*H_ + jt0 + g) * H_;
#pragma unroll
    for (int kk = kbeg; kk < kbeg + 128; kk += 16) {
        uint32_t af[2][4];
#pragma unroll
        for (int mt = 0; mt < 2; mt++) {
            const __half* ap = A + (size_t)(mt*16 + g) * H_ + kk + 2*tg;
            af[mt][0] = __ldcg((const unsigned*)ap);
            af[mt][1] = __ldcg((const unsigned*)(ap + 8*H_));
            af[mt][2] = __ldcg((const unsigned*)(ap + 8));
            af[mt][3] = __ldcg((const unsigned*)(ap + 8*H_ + 8));
        }
        uint32_t bf[2];
        bf[0] = __ldg((const unsigned*)(w0 + kk + 2*tg));
        bf[1] = __ldg((const unsigned*)(w0 + kk + 2*tg + 8));
        mma16(acc[0][0], af[0], bf);
        mma16(acc[1][0], af[1], bf);
        bf[0] = __ldg((const unsigned*)(w1 + kk + 2*tg));
        bf[1] = __ldg((const unsigned*)(w1 + kk + 2*tg + 8));
        mma16(acc[0][1], af[0], bf);
        mma16(acc[1][1], af[1], bf);
        bf[0] = __ldg((const unsigned*)(w2 + kk + 2*tg));
        bf[1] = __ldg((const unsigned*)(w2 + kk + 2*tg + 8));
        mma16(acc[0][2], af[0], bf);
        mma16(acc[1][2], af[1], bf);
    }
}

__device__ __forceinline__ void reduce_acc(const float acc[2][3][4],
        float* s_red, float* s_out, int lane, int warp)
{
    int g = lane >> 2, tg = lane & 3;
#pragma unroll
    for (int mt = 0; mt < 2; mt++)
#pragma unroll
    for (int nt = 0; nt < 3; nt++)
#pragma unroll
    for (int q = 0; q < 4; q++) {
        int row = mt*16 + g + ((q >> 1) << 3);
        int col = nt*8 + 2*tg + (q & 1);
        s_red[warp*768 + row*24 + col] = acc[mt][nt][q];
    }
    __syncthreads();
    int tid = threadIdx.x;
    for (int e = tid; e < 768; e += 256) {
        float s = 0.f;
#pragma unroll
        for (int w = 0; w < 8; w++) s += s_red[w*768 + e];
        s_out[e] = s;
    }
    __syncthreads();
}

__device__ __forceinline__ float sigf(float x) { return 1.f / (1.f + expf(-x)); }

// ---------------- persistent encoder (R14-proven) ----------------
__global__ void __launch_bounds__(256) k_enc(
    const float* __restrict__ bhh0, const float* __restrict__ bih1,
    const float* __restrict__ bhh1)
{
    __shared__ float s_red[8*768];
    __shared__ float s_g0[768];
    __shared__ float s_gi[768];
    __shared__ float s_gh[768];
    int tid = threadIdx.x, lane = tid & 31, warp = tid >> 5;
    int jt0 = blockIdx.x * 8;
    int cb = tid >> 3, cj = tid & 7;
    unsigned target = 0;

    int gidx = blockIdx.x * 256 + tid;
    g_h0[0][gidx] = 0.f;
    g_h1[0][gidx] = 0.f;
    g_h0h[0][gidx] = __float2half_rn(0.f);
    g_h1h[0][gidx] = __float2half_rn(0.f);
    gbar(target);

    for (int t = 0; t <= S_; t++) {
        int p = t & 1;
        if (t < S_) {
            float a[2][3][4] = {};
            gemv16(a, g_h0h[p], g_wh[0], jt0, lane, warp);
            reduce_acc(a, s_red, s_g0, lane, warp);
        }
        if (t > 0) {
            float a[2][3][4] = {};
            gemv16(a, g_h0h[p], g_wh[1], jt0, lane, warp);
            reduce_acc(a, s_red, s_gi, lane, warp);
            float a2[2][3][4] = {};
            gemv16(a2, g_h1h[1-p], g_wh[2], jt0, lane, warp);
            reduce_acc(a2, s_red, s_gh, lane, warp);
        }
        if (t < S_) {
            int j = jt0 + cj;
            const float* gi = g_gi0 + ((size_t)cb * S_ + t) * H3_;
            float r = sigf(gi[j]      + s_g0[cb*24 + cj]      + bhh0[j]);
            float z = sigf(gi[H_ + j] + s_g0[cb*24 + 8 + cj]  + bhh0[H_ + j]);
            float ghn =                 s_g0[cb*24 + 16 + cj] + bhh0[2*H_ + j];
            float n = tanhf(gi[2*H_ + j] + r * ghn);
            float hp = __ldcg(&g_h0[p][cb*H_ + j]);
            float h = (1.f - z) * n + z * hp;
            g_h0[1-p][cb*H_ + j] = h;
            g_h0h[1-p][cb*H_ + j] = __float2half_rn(h);
        }
        if (t > 0) {
            int j = jt0 + cj;
            float r = sigf(s_gi[cb*24 + cj]      + bih1[j]
                         + s_gh[cb*24 + cj]      + bhh1[j]);
            float z = sigf(s_gi[cb*24 + 8 + cj]  + bih1[H_ + j]
                         + s_gh[cb*24 + 8 + cj]  + bhh1[H_ + j]);
            float gin = s_gi[cb*24 + 16 + cj] + bih1[2*H_ + j];
            float ghn = s_gh[cb*24 + 16 + cj] + bhh1[2*H_ + j];
            float n = tanhf(gin + r * ghn);
            float hp = __ldcg(&g_h1[1-p][cb*H_ + j]);
            float h = (1.f - z) * n + z * hp;
            g_h1[p][cb*H_ + j] = h;
            g_h1h[p][cb*H_ + j] = __float2half_rn(h);
            g_ench[((size_t)cb * S_ + (t-1)) * H_ + j] = __float2half_rn(h);
        }
        gbar(target);
    }
}

// ---------------- persistent decoder (R14-proven; hc copy now fp16) ----------------
__global__ void __launch_bounds__(256) k_dec(
    const int* __restrict__ src_ids,
    const float* __restrict__ bhh0, const float* __restrict__ bih1,
    const float* __restrict__ bhh1)
{
    __shared__ float s_red[8*768];
    __shared__ float s_gi[768];
    __shared__ float s_gh[768];
    __shared__ float s_ev[S_];
    __shared__ float s_mxv[2];
    int tid = threadIdx.x, lane = tid & 31, warp = tid >> 5;
    int nb = blockIdx.x;
    int jt0 = nb * 8;
    int cb = tid >> 3, cj = tid & 7;
    int b = nb >> 2, hq = nb & 3;
    unsigned target = 0;

    for (int t = 0; t < TD; t++) {
        int p = t & 1;
        {   // ---- P_ab: scores (fp16 proj, fp16 h1) + softmax + ctx (fp16 enc)
            float* hc = s_red;
            const __half2* h1v = (const __half2*)(g_h1h[p] + b*H_);
            for (int i2 = tid; i2 < H_/2; i2 += 256) {
                unsigned u = __ldcg((const unsigned*)(h1v + i2));
                __half2 hh = *(__half2*)&u;
                float2 f = __half22float2(hh);
                hc[2*i2] = f.x;
                hc[2*i2 + 1] = f.y;
            }
            __syncthreads();
#pragma unroll
            for (int ss = 0; ss < 8; ss++) {
                int s = warp * 8 + ss;
                const __half2* ph2 = (const __half2*)(g_projh + (size_t)(b*S_ + s)*H_);
                float acc = 0.f;
#pragma unroll 8
                for (int k2 = lane; k2 < H_/2; k2 += 32) {
                    float2 pf = __half22float2(__ldg(ph2 + k2));
                    acc += pf.x * hc[2*k2] + pf.y * hc[2*k2 + 1];
                }
#pragma unroll
                for (int o = 16; o; o >>= 1) acc += __shfl_xor_sync(0xffffffffu, acc, o);
                if (lane == 0)
                    s_ev[s] = (src_ids[b*S_ + s] != 0) ? acc : -1e9f;
            }
            __syncthreads();
            if (tid == 0) {
                float mx = -1e30f;
#pragma unroll
                for (int s = 0; s < S_; s++) mx = fmaxf(mx, s_ev[s]);
                s_mxv[0] = mx;
            }
            __syncthreads();
            if (tid < S_) s_ev[tid] = expf(s_ev[tid] - s_mxv[0]);
            __syncthreads();
            if (tid == 0) {
                float su = 0.f;
#pragma unroll
                for (int s = 0; s < S_; s++) su += s_ev[s];
                s_mxv[1] = 1.f / su;
            }
            __syncthreads();
            float inv = s_mxv[1];
            int h = hq * 256 + tid;
            const __half* eph = g_ench + (size_t)b * S_ * H_ + h;
            float a = 0.f;
#pragma unroll 8
            for (int s = 0; s < S_; s++)
                a += s_ev[s] * __half2float(__ldg(eph + (size_t)s * H_));
            a *= inv;
            __half ah = __float2half_rn(a);
            g_xh[b*H_ + h] = ah;
            g_cath[((size_t)t * B_ + b) * (2*H_) + H_ + h] = ah;
        }
        gbar(target);
        {   // ---- P_c: layer0
            float ai[2][3][4] = {};
            float ahh[2][3][4] = {};
            gemv16(ai,  g_xh,      g_wh[4], jt0, lane, warp);
            gemv16(ahh, g_h0h[p],  g_wh[3], jt0, lane, warp);
            reduce_acc(ai,  s_red, s_gi, lane, warp);
            reduce_acc(ahh, s_red, s_gh, lane, warp);
            int j = jt0 + cj;
            const float* ge = g_giemb + ((size_t)t * B_ + cb) * H3_;
            float r = sigf(s_gi[cb*24 + cj]      + ge[j]
                         + s_gh[cb*24 + cj]      + bhh0[j]);
            float z = sigf(s_gi[cb*24 + 8 + cj]  + ge[H_ + j]
                         + s_gh[cb*24 + 8 + cj]  + bhh0[H_ + j]);
            float ghn = s_gh[cb*24 + 16 + cj] + bhh0[2*H_ + j];
            float gin = s_gi[cb*24 + 16 + cj] + ge[2*H_ + j];
            float n = tanhf(gin + r * ghn);
            float hp = __ldcg(&g_h0[p][cb*H_ + j]);
            float h = (1.f - z) * n + z * hp;
            g_h0[1-p][cb*H_ + j] = h;
            g_h0h[1-p][cb*H_ + j] = __float2half_rn(h);
        }
        gbar(target);
        {   // ---- P_d: layer1
            float ai[2][3][4] = {};
            float ahh[2][3][4] = {};
            gemv16(ai,  g_h0h[1-p], g_wh[5], jt0, lane, warp);
            gemv16(ahh, g_h1h[p],   g_wh[6], jt0, lane, warp);
            reduce_acc(ai,  s_red, s_gi, lane, warp);
            reduce_acc(ahh, s_red, s_gh, lane, warp);
            int j = jt0 + cj;
            float r = sigf(s_gi[cb*24 + cj]      + bih1[j]
                         + s_gh[cb*24 + cj]      + bhh1[j]);
            float z = sigf(s_gi[cb*24 + 8 + cj]  + bih1[H_ + j]
                         + s_gh[cb*24 + 8 + cj]  + bhh1[H_ + j]);
            float gin = s_gi[cb*24 + 16 + cj] + bih1[2*H_ + j];
            float ghn = s_gh[cb*24 + 16 + cj] + bhh1[2*H_ + j];
            float n = tanhf(gin + r * ghn);
            float hp = __ldcg(&g_h1[p][cb*H_ + j]);
            float h = (1.f - z) * n + z * hp;
            g_h1[1-p][cb*H_ + j] = h;
            g_h1h[1-p][cb*H_ + j] = __float2half_rn(h);
            g_cath[((size_t)t * B_ + cb) * (2*H_) + j] = __float2half_rn(h);
        }
        gbar(target);
    }
}

// ---------------- fp16 GEMM (R14-proven), 3 store modes ----------------
template<int MODE>
__global__ __launch_bounds__(256, 2)
void k_gemm16(const __half* __restrict__ A, int lda,
              const __half* __restrict__ W, int ldw,
              const float* __restrict__ bias, float* __restrict__ Cf,
              __half* __restrict__ Ch, int M, int N, int K)
{
    __shared__ __half As[2][128*40];
    __shared__ __half Bs[2][128*40];
    const int tid = threadIdx.x;
    const int m0 = blockIdx.x * 128;
    const int n0 = blockIdx.y * 128;
    const int warp = tid >> 5, lane = tid & 31;
    const int g = lane >> 2, tg = lane & 3;
    const int wm = (warp >> 2) * 64, wn = (warp & 3) * 32;

    const int lrow = tid >> 1;
    const int lo   = (tid & 1) * 16;
    int ar = m0 + lrow; if (ar >= M) ar = M - 1;
    const __half* ag = A + (size_t)ar * lda + lo;
    const __half* bg = W + (size_t)(n0 + lrow) * ldw + lo;
    uint32_t sa = (uint32_t)__cvta_generic_to_shared(&As[0][lrow*40 + lo]);
    uint32_t sb = (uint32_t)__cvta_generic_to_shared(&Bs[0][lrow*40 + lo]);
    const uint32_t ssz = 128*40*2;

    float acc[4][4][4];
#pragma unroll
    for (int i = 0; i < 4; i++)
#pragma unroll
        for (int j = 0; j < 4; j++)
#pragma unroll
            for (int q = 0; q < 4; q++) acc[i][j][q] = 0.f;

    auto issue = [&](int st, int c) {
        uint32_t so = st ? ssz : 0;
        const __half* p0 = ag + c*32;
        const __half* p1 = bg + c*32;
        asm volatile("cp.async.cg.shared.global [%0], [%1], 16;\n" :: "r"(sa+so), "l"(p0));
        asm volatile("cp.async.cg.shared.global [%0], [%1], 16;\n" :: "r"(sa+so+16), "l"(p0+8));
        asm volatile("cp.async.cg.shared.global [%0], [%1], 16;\n" :: "r"(sb+so), "l"(p1));
        asm volatile("cp.async.cg.shared.global [%0], [%1], 16;\n" :: "r"(sb+so+16), "l"(p1+8));
    };

    const int nchunk = K / 32;
    issue(0, 0);
    asm volatile("cp.async.commit_group;\n");

    for (int c = 0; c < nchunk; c++) {
        if (c + 1 < nchunk) issue((c + 1) & 1, c + 1);
        asm volatile("cp.async.commit_group;\n");
        asm volatile("cp.async.wait_group 1;\n");
        __syncthreads();
        const __half* as = As[c & 1];
        const __half* bs = Bs[c & 1];
#pragma unroll
        for (int ks = 0; ks < 32; ks += 16) {
            uint32_t af[4][4], bf[4][2];
#pragma unroll
            for (int i = 0; i < 4; i++) {
                int r = wm + i*16 + g;
                af[i][0] = *(const uint32_t*)&as[r*40 + ks + 2*tg];
                af[i][1] = *(const uint32_t*)&as[(r+8)*40 + ks + 2*tg];
                af[i][2] = *(const uint32_t*)&as[r*40 + ks + 2*tg + 8];
                af[i][3] = *(const uint32_t*)&as[(r+8)*40 + ks + 2*tg + 8];
            }
#pragma unroll
            for (int j = 0; j < 4; j++) {
                int cc = wn + j*8 + g;
                bf[j][0] = *(const uint32_t*)&bs[cc*40 + ks + 2*tg];
                bf[j][1] = *(const uint32_t*)&bs[cc*40 + ks + 2*tg + 8];
            }
#pragma unroll
            for (int i = 0; i < 4; i++)
#pragma unroll
                for (int j = 0; j < 4; j++)
                    mma16(acc[i][j], af[i], bf[j]);
        }
        __syncthreads();
    }

#pragma unroll
    for (int i = 0; i < 4; i++) {
#pragma unroll
        for (int j = 0; j < 4; j++) {
            int n = n0 + wn + j*8 + 2*tg;
            float bv0 = (MODE == 2) ? 0.f : bias[n];
            float bv1 = (MODE == 2) ? 0.f : bias[n + 1];
#pragma unroll
            for (int half = 0; half < 2; half++) {
                int m = m0 + wm + i*16 + g + half*8;
                float v0 = acc[i][j][half*2]     + bv0;
                float v1 = acc[i][j][half*2 + 1] + bv1;
                if (m < M) {
                    if (MODE == 0) {
                        float* o = Cf + (size_t)m * N + n;
                        o[0] = v0; o[1] = v1;
                    } else if (MODE == 1) {
                        int bb = m & 31, tt = m >> 5;
                        float* o = Cf + (size_t)bb*TD*V_ + (size_t)tt*V_ + n;
                        o[0] = v0; o[1] = v1;
                    } else {
                        *(__half2*)(Ch + (size_t)m * N + n) = __floats2half2_rn(v0, v1);
                    }
                }
            }
        }
    }
}

// ---------------- host ----------------
extern "C" void kernel_launch(void* const* d_in, const int* in_sizes, int n_in,
                              void* d_out, int out_size)
{
    const int*   src_ids  = (const int*)d_in[0];
    const int*   tgt_ids  = (const int*)d_in[2];
    const float* enc_emb  = (const float*)d_in[3];
    const float* dec_emb  = (const float*)d_in[4];
    const float* enc_wih0 = (const float*)d_in[5];
    const float* enc_whh0 = (const float*)d_in[6];
    const float* enc_bih0 = (const float*)d_in[7];
    const float* enc_bhh0 = (const float*)d_in[8];
    const float* enc_wih1 = (const float*)d_in[9];
    const float* enc_whh1 = (const float*)d_in[10];
    const float* enc_bih1 = (const float*)d_in[11];
    const float* enc_bhh1 = (const float*)d_in[12];
    const float* dec_wih0 = (const float*)d_in[13];
    const float* dec_whh0 = (const float*)d_in[14];
    const float* dec_bih0 = (const float*)d_in[15];
    const float* dec_bhh0 = (const float*)d_in[16];
    const float* dec_wih1 = (const float*)d_in[17];
    const float* dec_whh1 = (const float*)d_in[18];
    const float* dec_bih1 = (const float*)d_in[19];
    const float* dec_bhh1 = (const float*)d_in[20];
    const float* attn_w   = (const float*)d_in[21];
    const float* out_w    = (const float*)d_in[22];
    const float* out_b    = (const float*)d_in[23];
    float* out = (float*)d_out;

    float *gi0, *giemb;
    __half *embh, *dembh, *wih0eh, *wih0dh, *attnh, *ench, *projh, *cath, *owh;
    cudaGetSymbolAddress((void**)&gi0,    g_gi0);
    cudaGetSymbolAddress((void**)&giemb,  g_giemb);
    cudaGetSymbolAddress((void**)&embh,   g_embh);
    cudaGetSymbolAddress((void**)&dembh,  g_dembh);
    cudaGetSymbolAddress((void**)&wih0eh, g_wih0eh);
    cudaGetSymbolAddress((void**)&wih0dh, g_wih0dh);
    cudaGetSymbolAddress((void**)&attnh,  g_attnh);
    cudaGetSymbolAddress((void**)&ench,   g_ench);
    cudaGetSymbolAddress((void**)&projh,  g_projh);
    cudaGetSymbolAddress((void**)&cath,   g_cath);
    cudaGetSymbolAddress((void**)&owh,    g_owh);

    // prep
    k_init<<<(B_*S_*E_ + 255)/256, 256>>>(src_ids, enc_emb);
    k_demb<<<(TD*B_*E_ + 255)/256, 256>>>(tgt_ids, dec_emb);
    k_wconv<<<dim3(H3_*H_/256, 7), 256>>>(enc_whh0, enc_wih1, enc_whh1,
                                          dec_whh0, dec_wih0, dec_wih1, dec_whh1);
    k_wconv2<<<dim3(H3_*E_/256, 3), 256>>>(enc_wih0, dec_wih0, attn_w);
    k_owconv<<<(V_*2*H_/8 + 255)/256, 256>>>(out_w);

    // batched input-gate GEMMs (fp16)
    k_gemm16<0><<<dim3((B_*S_)/128, H3_/128), 256>>>(
        embh, E_, wih0eh, E_, enc_bih0, gi0, nullptr, B_*S_, H3_, E_);
    k_gemm16<0><<<dim3((TD*B_ + 127)/128, H3_/128), 256>>>(
        dembh, E_, wih0dh, E_, dec_bih0, giemb, nullptr, TD*B_, H3_, E_);

    // persistent encoder
    k_reset<<<1, 1>>>();
    k_enc<<<NBLK, 256>>>(enc_bhh0, enc_bih1, enc_bhh1);

    // attention projection (fp16 in/out)
    k_gemm16<2><<<dim3((B_*S_)/128, H_/128), 256>>>(
        ench, H_, attnh, H_, nullptr, nullptr, projh, B_*S_, H_, H_);

    // persistent decoder
    k_reset<<<1, 1>>>();
    k_dec<<<NBLK, 256>>>(src_ids, dec_bhh0, dec_bih1, dec_bhh1);

    // output projection (fp16, scatter to (B,TD,V))
    k_gemm16<1><<<dim3((TD*B_ + 127)/128, V_/128), 256>>>(
        cath, 2*H_, owh, 2*H_, out_b, out, nullptr, TD*B_, V_, 2*H_);
}

// round 17
// speedup vs baseline: 1.4343x; 1.0522x over previous
#include <cuda_runtime.h>
#include <cuda_fp16.h>
#include <math.h>
#include <stdint.h>

#define B_   32
#define S_   64
#define T_   48
#define TD   47
#define V_   32000
#define E_   512
#define H_   1024
#define H3_  3072
#define NBLK 128

// ---------------- device scratch ----------------
__device__ float g_gi0  [B_*S_*H3_];
__device__ float g_giemb[TD*B_*H3_];
__device__ float g_h0   [2][B_*H_];
__device__ float g_h1   [2][B_*H_];
__device__ unsigned g_count;
// fp16 operands
__device__ __half g_embh [B_*S_*E_];
__device__ __half g_dembh[TD*B_*E_];
__device__ __half g_wih0eh[H3_*E_];
__device__ __half g_wih0dh[H3_*E_];
__device__ __half g_attnh [H_*H_];
__device__ __half g_ench [B_*S_*H_];
__device__ __half g_projh[B_*S_*H_];
__device__ __half g_wh[7][H3_*H_];
__device__ __half g_h0h[2][B_*H_];
__device__ __half g_h1h[2][B_*H_];
__device__ __half g_xh [B_*H_];
__device__ __half g_cath[TD*B_*2*H_];
__device__ __half g_owh[(size_t)V_*2*H_];

__global__ void k_reset() { g_count = 0u; }

// ---------------- helpers ----------------
__device__ __forceinline__ void mma16(float c[4], const uint32_t a[4], const uint32_t b[2]) {
    asm volatile(
        "mma.sync.aligned.m16n8k16.row.col.f32.f16.f16.f32 "
        "{%0,%1,%2,%3}, {%4,%5,%6,%7}, {%8,%9}, {%0,%1,%2,%3};\n"
        : "+f"(c[0]), "+f"(c[1]), "+f"(c[2]), "+f"(c[3])
        : "r"(a[0]), "r"(a[1]), "r"(a[2]), "r"(a[3]), "r"(b[0]), "r"(b[1]));
}

// ---------------- prep ----------------
__global__ void k_init(const int* __restrict__ src_ids, const float* __restrict__ enc_emb)
{
    int idx = blockIdx.x * blockDim.x + threadIdx.x;
    if (idx < B_*S_*E_) {
        int m = idx >> 9, k = idx & 511;
        g_embh[idx] = __float2half_rn(enc_emb[(size_t)src_ids[m] * E_ + k]);
    }
}
__global__ void k_demb(const int* __restrict__ tgt_ids, const float* __restrict__ dec_emb)
{
    int idx = blockIdx.x * blockDim.x + threadIdx.x;
    if (idx >= TD*B_*E_) return;
    int m = idx >> 9, k = idx & 511;
    int b = m & 31, t = m >> 5;
    g_dembh[idx] = __float2half_rn(dec_emb[(size_t)tgt_ids[b*T_ + t] * E_ + k]);
}
__global__ void k_wconv(const float* __restrict__ e_whh0, const float* __restrict__ e_wih1,
                        const float* __restrict__ e_whh1, const float* __restrict__ d_whh0,
                        const float* __restrict__ d_wih0, const float* __restrict__ d_wih1,
                        const float* __restrict__ d_whh1)
{
    int y = blockIdx.y;
    int idx = blockIdx.x * 256 + threadIdx.x;
    float v;
    if (y == 4) {
        int r = idx >> 10, c = idx & 1023;
        v = d_wih0[(size_t)r * (E_+H_) + E_ + c];
    } else {
        const float* src = (y==0) ? e_whh0 : (y==1) ? e_wih1 : (y==2) ? e_whh1
                         : (y==3) ? d_whh0 : (y==5) ? d_wih1 : d_whh1;
        v = src[idx];
    }
    g_wh[y][idx] = __float2half_rn(v);
}
__global__ void k_wconv2(const float* __restrict__ e_wih0, const float* __restrict__ d_wih0,
                         const float* __restrict__ attn_w)
{
    int y = blockIdx.y;
    int idx = blockIdx.x * 256 + threadIdx.x;
    if (y == 0) {
        g_wih0eh[idx] = __float2half_rn(e_wih0[idx]);
    } else if (y == 1) {
        int r = idx >> 9, c = idx & 511;
        g_wih0dh[idx] = __float2half_rn(d_wih0[(size_t)r * (E_+H_) + c]);
    } else {
        if (idx < H_*H_) g_attnh[idx] = __float2half_rn(attn_w[idx]);
    }
}
__global__ void k_owconv(const float* __restrict__ out_w)
{
    size_t i = ((size_t)blockIdx.x * 256 + threadIdx.x) * 8;
    float4 a = *(const float4*)(out_w + i);
    float4 b = *(const float4*)(out_w + i + 4);
    __half2 h0 = __floats2half2_rn(a.x, a.y);
    __half2 h1 = __floats2half2_rn(a.z, a.w);
    __half2 h2 = __floats2half2_rn(b.x, b.y);
    __half2 h3 = __floats2half2_rn(b.z, b.w);
    uint4 o;
    o.x = *(uint32_t*)&h0; o.y = *(uint32_t*)&h1;
    o.z = *(uint32_t*)&h2; o.w = *(uint32_t*)&h3;
    *(uint4*)(g_owh + i) = o;
}

// ---------------- grid barrier (proven) ----------------
__device__ __forceinline__ void gbar(unsigned &target) {
    __threadfence();
    __syncthreads();
    if (threadIdx.x == 0) {
        atomicAdd(&g_count, 1u);
        target += NBLK;
        while (*(volatile unsigned*)&g_count < target) { }
    }
    __syncthreads();
}

// ---------------- fp16 GEMV pass (R12-proven) ----------------
__device__ __forceinline__ void gemv16(float acc[2][3][4],
        const __half* __restrict__ A, const __half* __restrict__ W,
        int jt0, int lane, int warp)
{
    int g = lane >> 2, tg = lane & 3;
    int kbeg = warp * 128;
    const __half* w0 = W + (size_t)(jt0 + g) * H_;
    const __half* w1 = W + (size_t)(H_ + jt0 + g) * H_;
    const __half* w2 = W + (size_t)(2*H_ + jt0 + g) * H_;
#pragma unroll
    for (int kk = kbeg; kk < kbeg + 128; kk += 16) {
        uint32_t af[2][4];
#pragma unroll
        for (int mt = 0; mt < 2; mt++) {
            const __half* ap = A + (size_t)(mt*16 + g) * H_ + kk + 2*tg;
            af[mt][0] = __ldcg((const unsigned*)ap);
            af[mt][1] = __ldcg((const unsigned*)(ap + 8*H_));
            af[mt][2] = __ldcg((const unsigned*)(ap + 8));
            af[mt][3] = __ldcg((const unsigned*)(ap + 8*H_ + 8));
        }
        uint32_t bf[2];
        bf[0] = __ldg((const unsigned*)(w0 + kk + 2*tg));
        bf[1] = __ldg((const unsigned*)(w0 + kk + 2*tg + 8));
        mma16(acc[0][0], af[0], bf);
        mma16(acc[1][0], af[1], bf);
        bf[0] = __ldg((const unsigned*)(w1 + kk + 2*tg));
        bf[1] = __ldg((const unsigned*)(w1 + kk + 2*tg + 8));
        mma16(acc[0][1], af[0], bf);
        mma16(acc[1][1], af[1], bf);
        bf[0] = __ldg((const unsigned*)(w2 + kk + 2*tg));
        bf[1] = __ldg((const unsigned*)(w2 + kk + 2*tg + 8));
        mma16(acc[0][2], af[0], bf);
        mma16(acc[1][2], af[1], bf);
    }
}

__device__ __forceinline__ void reduce_acc(const float acc[2][3][4],
        float* s_red, float* s_out, int lane, int warp)
{
    int g = lane >> 2, tg = lane & 3;
#pragma unroll
    for (int mt = 0; mt < 2; mt++)
#pragma unroll
    for (int nt = 0; nt < 3; nt++)
#pragma unroll
    for (int q = 0; q < 4; q++) {
        int row = mt*16 + g + ((q >> 1) << 3);
        int col = nt*8 + 2*tg + (q & 1);
        s_red[warp*768 + row*24 + col] = acc[mt][nt][q];
    }
    __syncthreads();
    int tid = threadIdx.x;
    for (int e = tid; e < 768; e += 256) {
        float s = 0.f;
#pragma unroll
        for (int w = 0; w < 8; w++) s += s_red[w*768 + e];
        s_out[e] = s;
    }
    __syncthreads();
}

__device__ __forceinline__ float sigf(float x) { return 1.f / (1.f + expf(-x)); }

// ---------------- persistent encoder (gemv,gemv -> reduce,reduce) ----------------
__global__ void __launch_bounds__(256) k_enc(
    const float* __restrict__ bhh0, const float* __restrict__ bih1,
    const float* __restrict__ bhh1)
{
    __shared__ float s_red[8*768];
    __shared__ float s_g0[768];
    __shared__ float s_gi[768];
    __shared__ float s_gh[768];
    int tid = threadIdx.x, lane = tid & 31, warp = tid >> 5;
    int jt0 = blockIdx.x * 8;
    int cb = tid >> 3, cj = tid & 7;
    unsigned target = 0;

    int gidx = blockIdx.x * 256 + tid;
    g_h0[0][gidx] = 0.f;
    g_h1[0][gidx] = 0.f;
    g_h0h[0][gidx] = __float2half_rn(0.f);
    g_h1h[0][gidx] = __float2half_rn(0.f);
    gbar(target);

    for (int t = 0; t <= S_; t++) {
        int p = t & 1;
        float a0[2][3][4] = {};
        float a1[2][3][4] = {};
        float a2[2][3][4] = {};
        if (t < S_) gemv16(a0, g_h0h[p], g_wh[0], jt0, lane, warp);
        if (t > 0) {
            gemv16(a1, g_h0h[p], g_wh[1], jt0, lane, warp);
            gemv16(a2, g_h1h[1-p], g_wh[2], jt0, lane, warp);
        }
        if (t < S_) reduce_acc(a0, s_red, s_g0, lane, warp);
        if (t > 0) {
            reduce_acc(a1, s_red, s_gi, lane, warp);
            reduce_acc(a2, s_red, s_gh, lane, warp);
        }
        if (t < S_) {
            int j = jt0 + cj;
            const float* gi = g_gi0 + ((size_t)cb * S_ + t) * H3_;
            float r = sigf(gi[j]      + s_g0[cb*24 + cj]      + bhh0[j]);
            float z = sigf(gi[H_ + j] + s_g0[cb*24 + 8 + cj]  + bhh0[H_ + j]);
            float ghn =                 s_g0[cb*24 + 16 + cj] + bhh0[2*H_ + j];
            float n = tanhf(gi[2*H_ + j] + r * ghn);
            float hp = __ldcg(&g_h0[p][cb*H_ + j]);
            float h = (1.f - z) * n + z * hp;
            g_h0[1-p][cb*H_ + j] = h;
            g_h0h[1-p][cb*H_ + j] = __float2half_rn(h);
        }
        if (t > 0) {
            int j = jt0 + cj;
            float r = sigf(s_gi[cb*24 + cj]      + bih1[j]
                         + s_gh[cb*24 + cj]      + bhh1[j]);
            float z = sigf(s_gi[cb*24 + 8 + cj]  + bih1[H_ + j]
                         + s_gh[cb*24 + 8 + cj]  + bhh1[H_ + j]);
            float gin = s_gi[cb*24 + 16 + cj] + bih1[2*H_ + j];
            float ghn = s_gh[cb*24 + 16 + cj] + bhh1[2*H_ + j];
            float n = tanhf(gin + r * ghn);
            float hp = __ldcg(&g_h1[1-p][cb*H_ + j]);
            float h = (1.f - z) * n + z * hp;
            g_h1[p][cb*H_ + j] = h;
            g_h1h[p][cb*H_ + j] = __float2half_rn(h);
            g_ench[((size_t)cb * S_ + (t-1)) * H_ + j] = __float2half_rn(h);
        }
        gbar(target);
    }
}

// ---------------- persistent decoder ----------------
__global__ void __launch_bounds__(256) k_dec(
    const int* __restrict__ src_ids,
    const float* __restrict__ bhh0, const float* __restrict__ bih1,
    const float* __restrict__ bhh1)
{
    __shared__ float s_red[8*768];
    __shared__ float s_gi[768];
    __shared__ float s_gh[768];
    __shared__ float s_ev[S_];
    __shared__ float s_mxv[2];
    int tid = threadIdx.x, lane = tid & 31, warp = tid >> 5;
    int nb = blockIdx.x;
    int jt0 = nb * 8;
    int cb = tid >> 3, cj = tid & 7;
    int b = nb >> 2, hq = nb & 3;
    unsigned target = 0;

    for (int t = 0; t < TD; t++) {
        int p = t & 1;
        {   // ---- P_ab: scores (8B proj loads) + softmax + ctx (half2 loads)
            float* hc = s_red;
            const __half2* h1v = (const __half2*)(g_h1h[p] + b*H_);
            for (int i2 = tid; i2 < H_/2; i2 += 256) {
                unsigned u = __ldcg((const unsigned*)(h1v + i2));
                __half2 hh = *(__half2*)&u;
                float2 f = __half22float2(hh);
                hc[2*i2] = f.x;
                hc[2*i2 + 1] = f.y;
            }
            __syncthreads();
#pragma unroll
            for (int ss = 0; ss < 8; ss++) {
                int s = warp * 8 + ss;
                const uint2* ph4 = (const uint2*)(g_projh + (size_t)(b*S_ + s)*H_);
                float acc = 0.f;
#pragma unroll 8
                for (int k4 = lane; k4 < H_/4; k4 += 32) {
                    uint2 u = __ldg(ph4 + k4);
                    float2 f0 = __half22float2(*(__half2*)&u.x);
                    float2 f1 = __half22float2(*(__half2*)&u.y);
                    acc += f0.x * hc[4*k4]     + f0.y * hc[4*k4 + 1]
                         + f1.x * hc[4*k4 + 2] + f1.y * hc[4*k4 + 3];
                }
#pragma unroll
                for (int o = 16; o; o >>= 1) acc += __shfl_xor_sync(0xffffffffu, acc, o);
                if (lane == 0)
                    s_ev[s] = (src_ids[b*S_ + s] != 0) ? acc : -1e9f;
            }
            __syncthreads();
            if (tid == 0) {
                float mx = -1e30f;
#pragma unroll
                for (int s = 0; s < S_; s++) mx = fmaxf(mx, s_ev[s]);
                s_mxv[0] = mx;
            }
            __syncthreads();
            if (tid < S_) s_ev[tid] = expf(s_ev[tid] - s_mxv[0]);
            __syncthreads();
            if (tid == 0) {
                float su = 0.f;
#pragma unroll
                for (int s = 0; s < S_; s++) su += s_ev[s];
                s_mxv[1] = 1.f / su;
            }
            __syncthreads();
            float inv = s_mxv[1];
            if (tid < 128) {
                int h = hq * 256 + tid * 2;
                const __half2* eph2 = (const __half2*)(g_ench + (size_t)b * S_ * H_ + h);
                float a0 = 0.f, a1 = 0.f;
#pragma unroll 8
                for (int s = 0; s < S_; s++) {
                    float2 f = __half22float2(__ldg(eph2 + (size_t)s * (H_/2)));
                    a0 += s_ev[s] * f.x;
                    a1 += s_ev[s] * f.y;
                }
                __half2 ah = __floats2half2_rn(a0 * inv, a1 * inv);
                *(__half2*)(g_xh + b*H_ + h) = ah;
                *(__half2*)(g_cath + ((size_t)t * B_ + b) * (2*H_) + H_ + h) = ah;
            }
        }
        gbar(target);
        {   // ---- P_c: layer0
            float ai[2][3][4] = {};
            float ahh[2][3][4] = {};
            gemv16(ai,  g_xh,      g_wh[4], jt0, lane, warp);
            gemv16(ahh, g_h0h[p],  g_wh[3], jt0, lane, warp);
            reduce_acc(ai,  s_red, s_gi, lane, warp);
            reduce_acc(ahh, s_red, s_gh, lane, warp);
            int j = jt0 + cj;
            const float* ge = g_giemb + ((size_t)t * B_ + cb) * H3_;
            float r = sigf(s_gi[cb*24 + cj]      + ge[j]
                         + s_gh[cb*24 + cj]      + bhh0[j]);
            float z = sigf(s_gi[cb*24 + 8 + cj]  + ge[H_ + j]
                         + s_gh[cb*24 + 8 + cj]  + bhh0[H_ + j]);
            float ghn = s_gh[cb*24 + 16 + cj] + bhh0[2*H_ + j];
            float gin = s_gi[cb*24 + 16 + cj] + ge[2*H_ + j];
            float n = tanhf(gin + r * ghn);
            float hp = __ldcg(&g_h0[p][cb*H_ + j]);
            float h = (1.f - z) * n + z * hp;
            g_h0[1-p][cb*H_ + j] = h;
            g_h0h[1-p][cb*H_ + j] = __float2half_rn(h);
        }
        gbar(target);
        {   // ---- P_d: layer1
            float ai[2][3][4] = {};
            float ahh[2][3][4] = {};
            gemv16(ai,  g_h0h[1-p], g_wh[5], jt0, lane, warp);
            gemv16(ahh, g_h1h[p],   g_wh[6], jt0, lane, warp);
            reduce_acc(ai,  s_red, s_gi, lane, warp);
            reduce_acc(ahh, s_red, s_gh, lane, warp);
            int j = jt0 + cj;
            float r = sigf(s_gi[cb*24 + cj]      + bih1[j]
                         + s_gh[cb*24 + cj]      + bhh1[j]);
            float z = sigf(s_gi[cb*24 + 8 + cj]  + bih1[H_ + j]
                         + s_gh[cb*24 + 8 + cj]  + bhh1[H_ + j]);
            float gin = s_gi[cb*24 + 16 + cj] + bih1[2*H_ + j];
            float ghn = s_gh[cb*24 + 16 + cj] + bhh1[2*H_ + j];
            float n = tanhf(gin + r * ghn);
            float hp = __ldcg(&g_h1[p][cb*H_ + j]);
            float h = (1.f - z) * n + z * hp;
            g_h1[1-p][cb*H_ + j] = h;
            g_h1h[1-p][cb*H_ + j] = __float2half_rn(h);
            g_cath[((size_t)t * B_ + cb) * (2*H_) + j] = __float2half_rn(h);
        }
        gbar(target);
    }
}

// ---------------- fp16 GEMM (R14-proven), 3 store modes ----------------
template<int MODE>
__global__ __launch_bounds__(256, 2)
void k_gemm16(const __half* __restrict__ A, int lda,
              const __half* __restrict__ W, int ldw,
              const float* __restrict__ bias, float* __restrict__ Cf,
              __half* __restrict__ Ch, int M, int N, int K)
{
    __shared__ __half As[2][128*40];
    __shared__ __half Bs[2][128*40];
    const int tid = threadIdx.x;
    const int m0 = blockIdx.x * 128;
    const int n0 = blockIdx.y * 128;
    const int warp = tid >> 5, lane = tid & 31;
    const int g = lane >> 2, tg = lane & 3;
    const int wm = (warp >> 2) * 64, wn = (warp & 3) * 32;

    const int lrow = tid >> 1;
    const int lo   = (tid & 1) * 16;
    int ar = m0 + lrow; if (ar >= M) ar = M - 1;
    const __half* ag = A + (size_t)ar * lda + lo;
    const __half* bg = W + (size_t)(n0 + lrow) * ldw + lo;
    uint32_t sa = (uint32_t)__cvta_generic_to_shared(&As[0][lrow*40 + lo]);
    uint32_t sb = (uint32_t)__cvta_generic_to_shared(&Bs[0][lrow*40 + lo]);
    const uint32_t ssz = 128*40*2;

    float acc[4][4][4];
#pragma unroll
    for (int i = 0; i < 4; i++)
#pragma unroll
        for (int j = 0; j < 4; j++)
#pragma unroll
            for (int q = 0; q < 4; q++) acc[i][j][q] = 0.f;

    auto issue = [&](int st, int c) {
        uint32_t so = st ? ssz : 0;
        const __half* p0 = ag + c*32;
        const __half* p1 = bg + c*32;
        asm volatile("cp.async.cg.shared.global [%0], [%1], 16;\n" :: "r"(sa+so), "l"(p0));
        asm volatile("cp.async.cg.shared.global [%0], [%1], 16;\n" :: "r"(sa+so+16), "l"(p0+8));
        asm volatile("cp.async.cg.shared.global [%0], [%1], 16;\n" :: "r"(sb+so), "l"(p1));
        asm volatile("cp.async.cg.shared.global [%0], [%1], 16;\n" :: "r"(sb+so+16), "l"(p1+8));
    };

    const int nchunk = K / 32;
    issue(0, 0);
    asm volatile("cp.async.commit_group;\n");

    for (int c = 0; c < nchunk; c++) {
        if (c + 1 < nchunk) issue((c + 1) & 1, c + 1);
        asm volatile("cp.async.commit_group;\n");
        asm volatile("cp.async.wait_group 1;\n");
        __syncthreads();
        const __half* as = As[c & 1];
        const __half* bs = Bs[c & 1];
#pragma unroll
        for (int ks = 0; ks < 32; ks += 16) {
            uint32_t af[4][4], bf[4][2];
#pragma unroll
            for (int i = 0; i < 4; i++) {
                int r = wm + i*16 + g;
                af[i][0] = *(const uint32_t*)&as[r*40 + ks + 2*tg];
                af[i][1] = *(const uint32_t*)&as[(r+8)*40 + ks + 2*tg];
                af[i][2] = *(const uint32_t*)&as[r*40 + ks + 2*tg + 8];
                af[i][3] = *(const uint32_t*)&as[(r+8)*40 + ks + 2*tg + 8];
            }
#pragma unroll
            for (int j = 0; j < 4; j++) {
                int cc = wn + j*8 + g;
                bf[j][0] = *(const uint32_t*)&bs[cc*40 + ks + 2*tg];
                bf[j][1] = *(const uint32_t*)&bs[cc*40 + ks + 2*tg + 8];
            }
#pragma unroll
            for (int i = 0; i < 4; i++)
#pragma unroll
                for (int j = 0; j < 4; j++)
                    mma16(acc[i][j], af[i], bf[j]);
        }
        __syncthreads();
    }

#pragma unroll
    for (int i = 0; i < 4; i++) {
#pragma unroll
        for (int j = 0; j < 4; j++) {
            int n = n0 + wn + j*8 + 2*tg;
            float bv0 = (MODE == 2) ? 0.f : bias[n];
            float bv1 = (MODE == 2) ? 0.f : bias[n + 1];
#pragma unroll
            for (int half = 0; half < 2; half++) {
                int m = m0 + wm + i*16 + g + half*8;
                float v0 = acc[i][j][half*2]     + bv0;
                float v1 = acc[i][j][half*2 + 1] + bv1;
                if (m < M) {
                    if (MODE == 0) {
                        float* o = Cf + (size_t)m * N + n;
                        o[0] = v0; o[1] = v1;
                    } else if (MODE == 1) {
                        int bb = m & 31, tt = m >> 5;
                        float* o = Cf + (size_t)bb*TD*V_ + (size_t)tt*V_ + n;
                        o[0] = v0; o[1] = v1;
                    } else {
                        *(__half2*)(Ch + (size_t)m * N + n) = __floats2half2_rn(v0, v1);
                    }
                }
            }
        }
    }
}

// ---------------- host ----------------
extern "C" void kernel_launch(void* const* d_in, const int* in_sizes, int n_in,
                              void* d_out, int out_size)
{
    const int*   src_ids  = (const int*)d_in[0];
    const int*   tgt_ids  = (const int*)d_in[2];
    const float* enc_emb  = (const float*)d_in[3];
    const float* dec_emb  = (const float*)d_in[4];
    const float* enc_wih0 = (const float*)d_in[5];
    const float* enc_whh0 = (const float*)d_in[6];
    const float* enc_bih0 = (const float*)d_in[7];
    const float* enc_bhh0 = (const float*)d_in[8];
    const float* enc_wih1 = (const float*)d_in[9];
    const float* enc_whh1 = (const float*)d_in[10];
    const float* enc_bih1 = (const float*)d_in[11];
    const float* enc_bhh1 = (const float*)d_in[12];
    const float* dec_wih0 = (const float*)d_in[13];
    const float* dec_whh0 = (const float*)d_in[14];
    const float* dec_bih0 = (const float*)d_in[15];
    const float* dec_bhh0 = (const float*)d_in[16];
    const float* dec_wih1 = (const float*)d_in[17];
    const float* dec_whh1 = (const float*)d_in[18];
    const float* dec_bih1 = (const float*)d_in[19];
    const float* dec_bhh1 = (const float*)d_in[20];
    const float* attn_w   = (const float*)d_in[21];
    const float* out_w    = (const float*)d_in[22];
    const float* out_b    = (const float*)d_in[23];
    float* out = (float*)d_out;

    float *gi0, *giemb;
    __half *embh, *dembh, *wih0eh, *wih0dh, *attnh, *ench, *projh, *cath, *owh;
    cudaGetSymbolAddress((void**)&gi0,    g_gi0);
    cudaGetSymbolAddress((void**)&giemb,  g_giemb);
    cudaGetSymbolAddress((void**)&embh,   g_embh);
    cudaGetSymbolAddress((void**)&dembh,  g_dembh);
    cudaGetSymbolAddress((void**)&wih0eh, g_wih0eh);
    cudaGetSymbolAddress((void**)&wih0dh, g_wih0dh);
    cudaGetSymbolAddress((void**)&attnh,  g_attnh);
    cudaGetSymbolAddress((void**)&ench,   g_ench);
    cudaGetSymbolAddress((void**)&projh,  g_projh);
    cudaGetSymbolAddress((void**)&cath,   g_cath);
    cudaGetSymbolAddress((void**)&owh,    g_owh);

    // prep
    k_init<<<(B_*S_*E_ + 255)/256, 256>>>(src_ids, enc_emb);
    k_demb<<<(TD*B_*E_ + 255)/256, 256>>>(tgt_ids, dec_emb);
    k_wconv<<<dim3(H3_*H_/256, 7), 256>>>(enc_whh0, enc_wih1, enc_whh1,
                                          dec_whh0, dec_wih0, dec_wih1, dec_whh1);
    k_wconv2<<<dim3(H3_*E_/256, 3), 256>>>(enc_wih0, dec_wih0, attn_w);
    k_owconv<<<(V_*2*H_/8 + 255)/256, 256>>>(out_w);

    // batched input-gate GEMMs (fp16)
    k_gemm16<0><<<dim3((B_*S_)/128, H3_/128), 256>>>(
        embh, E_, wih0eh, E_, enc_bih0, gi0, nullptr, B_*S_, H3_, E_);
    k_gemm16<0><<<dim3((TD*B_ + 127)/128, H3_/128), 256>>>(
        dembh, E_, wih0dh, E_, dec_bih0, giemb, nullptr, TD*B_, H3_, E_);

    // persistent encoder
    k_reset<<<1, 1>>>();
    k_enc<<<NBLK, 256>>>(enc_bhh0, enc_bih1, enc_bhh1);

    // attention projection (fp16 in/out)
    k_gemm16<2><<<dim3((B_*S_)/128, H_/128), 256>>>(
        ench, H_, attnh, H_, nullptr, nullptr, projh, B_*S_, H_, H_);

    // persistent decoder
    k_reset<<<1, 1>>>();
    k_dec<<<NBLK, 256>>>(src_ids, dec_bhh0, dec_bih1, dec_bhh1);

    // output projection (fp16, scatter to (B,TD,V))
    k_gemm16<1><<<dim3((TD*B_ + 127)/128, V_/128), 256>>>(
        cath, 2*H_, owh, 2*H_, out_b, out, nullptr, TD*B_, V_, 2*H_);
}